// round 10
// baseline (speedup 1.0000x reference)
#include <cuda_runtime.h>

#define NMAX 256

// Scratch (allocation-free rule: __device__ globals)
// g_quad[(y*1024+x)*3 + {0,1,2}] packs the 2x2 bilinear corner quad at (x,y):
//   q0 = (r00, g00, b00, r10)
//   q1 = (g10, b10, r01, g01)
//   q2 = (b01, r11, g11, b11)
// where 00=(x,y), 10=(x+1,y), 01=(x,y+1), 11=(x+1,y+1), neighbors edge-clamped.
__device__ float4 g_quad[1024 * 1024 * 3];   // 48 MB
__device__ float  g_IM[NMAX * 6];            // inverse affine per face
__device__ int2   g_rowrange[28];            // t192 rows owned by each 8-row tile

__constant__ float c_SRC[5][10] = {
    {103.284f,100.23f, 115.234f,99.98f, 71.48f,138.014f, 102.314f,178.1f,   114.05f,179.404f},
    {90.062f,100.236f, 131.136f,101.744f,79.354f,136.222f,90.354f,172.38f,  128.492f,173.516f},
    {79.46f,102.276f,  144.54f,102.276f, 112.0f,136.986f, 84.926f,174.02f,  139.074f,174.02f},
    {93.69f,101.744f,  134.764f,100.236f,145.474f,136.222f,96.334f,173.516f,134.472f,172.38f},
    {109.592f,99.98f,  121.542f,100.23f, 153.346f,138.014f,110.776f,179.404f,122.514f,178.1f}
};

// ---------------------------------------------------------------------------
// est: Umeyama over 5 templates, argmin, invert, compose. One thread/face.
// ---------------------------------------------------------------------------
__device__ void est_face(const float* __restrict__ xs, float* __restrict__ out,
                         int n, long long off_imc, long long off_M)
{
    float px[5], py[5];
#pragma unroll
    for (int i = 0; i < 5; i++) { px[i] = xs[n*10 + 2*i]; py[i] = xs[n*10 + 2*i + 1]; }

    float smx = 0.f, smy = 0.f;
#pragma unroll
    for (int i = 0; i < 5; i++) { smx += px[i]; smy += py[i]; }
    smx *= 0.2f; smy *= 0.2f;

    float sdx[5], sdy[5], var_sum = 0.f;
#pragma unroll
    for (int i = 0; i < 5; i++) {
        sdx[i] = px[i] - smx; sdy[i] = py[i] - smy;
        var_sum += sdx[i]*sdx[i] + sdy[i]*sdy[i];
    }
    var_sum *= 0.2f;

    float bestE = 3.4e38f;
    float bM[6] = {0,0,0,0,0,0};

#pragma unroll
    for (int k = 0; k < 5; k++) {
        const float* D = c_SRC[k];
        float dmx = 0.f, dmy = 0.f;
#pragma unroll
        for (int i = 0; i < 5; i++) { dmx += D[2*i]; dmy += D[2*i+1]; }
        dmx *= 0.2f; dmy *= 0.2f;

        float A00 = 0.f, A01 = 0.f, A10 = 0.f, A11 = 0.f;
#pragma unroll
        for (int i = 0; i < 5; i++) {
            float ddx = D[2*i]   - dmx;
            float ddy = D[2*i+1] - dmy;
            A00 += ddx * sdx[i]; A01 += ddx * sdy[i];
            A10 += ddy * sdx[i]; A11 += ddy * sdy[i];
        }
        A00 *= 0.2f; A01 *= 0.2f; A10 *= 0.2f; A11 *= 0.2f;

        float det = A00*A11 - A01*A10;
        float s   = (det > 0.f) ? 1.f : ((det < 0.f) ? -1.f : 0.f);

        float E = (A00 + A11) * 0.5f;
        float F = (A00 - A11) * 0.5f;
        float G = (A10 + A01) * 0.5f;
        float H = (A10 - A01) * 0.5f;
        float Q  = hypotf(E, H);
        float Rr = hypotf(F, G);
        float sxv = Q + Rr;
        float syv = Q - Rr;
        float a1 = atan2f(G, F);
        float a2 = atan2f(H, E);
        float beta  = (a2 - a1) * 0.5f;
        float gamma = (a2 + a1) * 0.5f;
        float cg = cosf(gamma), sg = sinf(gamma);
        float cb = cosf(beta),  sb = sinf(beta);
        float sgn = (syv < 0.f) ? -1.f : 1.f;
        float V00 = cb,        V01 = -sb;
        float V10 = sb * sgn,  V11 = cb * sgn;
        float R00 = cg * V00 - sg * s * V10;
        float R01 = cg * V01 - sg * s * V11;
        float R10 = sg * V00 + cg * s * V10;
        float R11 = sg * V01 + cg * s * V11;

        float scale = (sxv + fabsf(syv) * s) / var_sum;
        float tx = dmx - scale * (R00 * smx + R01 * smy);
        float ty = dmy - scale * (R10 * smx + R11 * smy);
        float M00 = scale * R00, M01 = scale * R01;
        float M10 = scale * R10, M11 = scale * R11;

        float e = 0.f;
#pragma unroll
        for (int i = 0; i < 5; i++) {
            float rx = M00*px[i] + M01*py[i] + tx - D[2*i];
            float ry = M10*px[i] + M11*py[i] + ty - D[2*i+1];
            e += sqrtf(rx*rx + ry*ry);
        }
        if (e < bestE) {
            bestE = e;
            bM[0] = M00; bM[1] = M01; bM[2] = tx;
            bM[3] = M10; bM[4] = M11; bM[5] = ty;
        }
    }

    float det = bM[0]*bM[4] - bM[1]*bM[3];
    float ia  =  bM[4] / det;
    float ib  = -bM[1] / det;
    float ic  = -bM[3] / det;
    float idd =  bM[0] / det;
    float itx = -(ia * bM[2] + ib  * bM[5]);
    float ity = -(ic * bM[2] + idd * bM[5]);

    g_IM[n*6+0] = ia;  g_IM[n*6+1] = ib;  g_IM[n*6+2] = itx;
    g_IM[n*6+3] = ic;  g_IM[n*6+4] = idd; g_IM[n*6+5] = ity;

    float pa = 0.57142857f, pt = 32.f;
    float pdet = pa * pa;
    float pia  = pa / pdet;
    float pitx = -(pia * pt);
    float C00 = ia  * pia,  C01 = ib  * pia;
    float C10 = ic  * pia,  C11 = idd * pia;
    float CT0 = ia * pitx + ib  * pitx + itx;
    float CT1 = ic * pitx + idd * pitx + ity;

#pragma unroll
    for (int j = 0; j < 10; j++) out[n*10 + j] = xs[n*10 + j];
    float* oc = out + off_imc + (long long)n * 6;
    oc[0] = C00; oc[1] = C01; oc[2] = CT0; oc[3] = C10; oc[4] = C11; oc[5] = CT1;
    float* om = out + off_M + (long long)n * 6;
    om[0] = bM[0]; om[1] = bM[1]; om[2] = bM[2]; om[3] = bM[3]; om[4] = bM[4]; om[5] = bM[5];
}

// ---------------------------------------------------------------------------
// Kernel A (prep): blocks [0,4096): quad-pack build (1 px/thread)
//                  block 4096: est for all faces
//                  block 4097: t192 tile row-ranges
// ---------------------------------------------------------------------------
__global__ __launch_bounds__(256) void prep_kernel(const float* __restrict__ img,
                                                   const float* __restrict__ xs,
                                                   float* __restrict__ out,
                                                   int N, long long off_imc, long long off_M)
{
    int blk = blockIdx.x;
    int tid = threadIdx.x;

    if (blk < 4096) {
        int i = blk * 256 + tid;            // pixel id, i < 1048576
        int x = i & 1023;
        int y = i >> 10;
        int xp = min(x + 1, 1023);
        int yp = min(y + 1, 1023);
        const float* p00 = img + 3 * (y  * 1024 + x);
        const float* p10 = img + 3 * (y  * 1024 + xp);
        const float* p01 = img + 3 * (yp * 1024 + x);
        const float* p11 = img + 3 * (yp * 1024 + xp);
        float r00 = __ldg(p00+0), g00 = __ldg(p00+1), b00 = __ldg(p00+2);
        float r10 = __ldg(p10+0), g10 = __ldg(p10+1), b10 = __ldg(p10+2);
        float r01 = __ldg(p01+0), g01 = __ldg(p01+1), b01 = __ldg(p01+2);
        float r11 = __ldg(p11+0), g11 = __ldg(p11+1), b11 = __ldg(p11+2);
        g_quad[3*i+0] = make_float4(r00, g00, b00, r10);
        g_quad[3*i+1] = make_float4(g10, b10, r01, g01);
        g_quad[3*i+2] = make_float4(b01, r11, g11, b11);
    } else if (blk == 4096) {
        if (tid < N) est_face(xs, out, tid, off_imc, off_M);
    } else {
        __shared__ int s_lo[28], s_hi[28];
        if (tid < 28) { s_lo[tid] = 192; s_hi[tid] = -1; }
        __syncthreads();
        if (tid < 192) {
            float pa = 0.57142857f, pt = 32.f;
            float pdet = pa * pa;
            float pia  = pa / pdet;
            float pitx = -(pia * pt);
            float syf = pia * (float)tid + pitx;
            int y0 = (int)floorf(syf);
            int t = (y0 < 0) ? 0 : ((y0 >= 224) ? 27 : (y0 >> 3));
            atomicMin(&s_lo[t], tid);
            atomicMax(&s_hi[t], tid);
        }
        __syncthreads();
        if (tid < 28) g_rowrange[tid] = make_int2(s_lo[tid], s_hi[tid]);
    }
}

// ---------------------------------------------------------------------------
// Kernel B (fused): per (face, 8-row tile):
//   phase 1: bilinear-warp img -> 9-row t224 tile in smem (+u8 output, 8 rows)
//            interior px: 3 LDG.128 from quad-pack; OOB skip; border fallback
//   phase 2: 1.75x-zoom bilinear tile -> owned t192 rows
// ---------------------------------------------------------------------------
__global__ __launch_bounds__(256, 5) void fused_warp_kernel(const float* __restrict__ img,
                                                            float* __restrict__ out,
                                                            long long off_u8,
                                                            long long off_t192)
{
    __shared__ float sm[3][9][224];   // 24192 B tile (halo row included)
    __shared__ float sIM[6];
    __shared__ int   sRange[2];

    int blk  = blockIdx.x;
    int tile = blk % 28;
    int n    = blk / 28;
    int r0   = tile * 8;
    int tid  = threadIdx.x;

    if (tid < 6) sIM[tid] = g_IM[n*6 + tid];
    if (tid == 6) { int2 rr = g_rowrange[tile]; sRange[0] = rr.x; sRange[1] = rr.y; }
    __syncthreads();
    float i0 = sIM[0], i1 = sIM[1], i2 = sIM[2];
    float i3 = sIM[3], i4 = sIM[4], i5 = sIM[5];

    // ---- phase 1: fill t224 tile, 4 px per thread-item ----
    int rows   = (r0 + 8 < 224) ? 9 : 8;
    int items4 = rows * 56;                      // 56 groups of 4 px per row
    for (int it = tid; it < items4; it += 256) {
        int ry = it / 56;
        int xq = (it - ry * 56) * 4;
        int y  = r0 + ry;
        float gy = (float)y;

        float sxv[4], syv[4];
#pragma unroll
        for (int j = 0; j < 4; j++) {
            float gx = (float)(xq + j);
            sxv[j] = i0 * gx + i1 * gy + i2;
            syv[j] = i3 * gx + i4 * gy + i5;
        }

        // Group-level OOB skip (affine monotone along segment).
        bool group_zero =
            (sxv[0] <= -1.f   && sxv[3] <= -1.f)   ||
            (sxv[0] >= 1024.f && sxv[3] >= 1024.f) ||
            (syv[0] <= -1.f   && syv[3] <= -1.f)   ||
            (syv[0] >= 1024.f && syv[3] >= 1024.f);

        float rr[4], gg[4], bb[4];
        if (group_zero) {
#pragma unroll
            for (int j = 0; j < 4; j++) { rr[j] = 0.f; gg[j] = 0.f; bb[j] = 0.f; }
        } else {
            bool interior = (sxv[0] >= 0.f) & (sxv[0] < 1023.f) &
                            (sxv[3] >= 0.f) & (sxv[3] < 1023.f) &
                            (syv[0] >= 0.f) & (syv[0] < 1023.f) &
                            (syv[3] >= 0.f) & (syv[3] < 1023.f);
            if (interior) {
#pragma unroll
                for (int j = 0; j < 4; j++) {
                    float x0f = floorf(sxv[j]), y0f = floorf(syv[j]);
                    float fx = sxv[j] - x0f,    fy = syv[j] - y0f;
                    int x0 = (int)x0f, y0 = (int)y0f;
                    float w00 = (1.f - fx) * (1.f - fy);
                    float w10 = fx         * (1.f - fy);
                    float w01 = (1.f - fx) * fy;
                    float w11 = fx         * fy;
                    int base = (y0 * 1024 + x0) * 3;
                    float4 q0 = g_quad[base];
                    float4 q1 = g_quad[base + 1];
                    float4 q2 = g_quad[base + 2];
                    rr[j] = q0.x*w00 + q0.w*w10 + q1.z*w01 + q2.y*w11;
                    gg[j] = q0.y*w00 + q1.x*w10 + q1.w*w01 + q2.z*w11;
                    bb[j] = q0.z*w00 + q1.y*w10 + q2.x*w01 + q2.w*w11;
                }
            } else {
#pragma unroll
                for (int j = 0; j < 4; j++) {
                    // per-pixel OOB skip
                    if (sxv[j] <= -1.f || sxv[j] >= 1024.f ||
                        syv[j] <= -1.f || syv[j] >= 1024.f) {
                        rr[j] = 0.f; gg[j] = 0.f; bb[j] = 0.f;
                        continue;
                    }
                    float x0f = floorf(sxv[j]), y0f = floorf(syv[j]);
                    float fx = sxv[j] - x0f,    fy = syv[j] - y0f;
                    int x0 = (int)x0f, y0 = (int)y0f;
                    int x1 = x0 + 1,   y1 = y0 + 1;
                    const int W = 1024, H = 1024;
                    float vx0 = (x0 >= 0 && x0 < W) ? 1.f : 0.f;
                    float vx1 = (x1 >= 0 && x1 < W) ? 1.f : 0.f;
                    float vy0 = (y0 >= 0 && y0 < H) ? 1.f : 0.f;
                    float vy1 = (y1 >= 0 && y1 < H) ? 1.f : 0.f;
                    float w00 = (1.f - fx) * (1.f - fy) * vx0 * vy0;
                    float w10 = fx         * (1.f - fy) * vx1 * vy0;
                    float w01 = (1.f - fx) * fy         * vx0 * vy1;
                    float w11 = fx         * fy         * vx1 * vy1;
                    int x0c = min(max(x0, 0), W-1), x1c = min(max(x1, 0), W-1);
                    int y0c = min(max(y0, 0), H-1), y1c = min(max(y1, 0), H-1);
                    const float* p00 = img + 3 * (y0c * W + x0c);
                    const float* p10 = img + 3 * (y0c * W + x1c);
                    const float* p01 = img + 3 * (y1c * W + x0c);
                    const float* p11 = img + 3 * (y1c * W + x1c);
                    rr[j] = __ldg(p00+0)*w00 + __ldg(p10+0)*w10 + __ldg(p01+0)*w01 + __ldg(p11+0)*w11;
                    gg[j] = __ldg(p00+1)*w00 + __ldg(p10+1)*w10 + __ldg(p01+1)*w01 + __ldg(p11+1)*w11;
                    bb[j] = __ldg(p00+2)*w00 + __ldg(p10+2)*w10 + __ldg(p01+2)*w01 + __ldg(p11+2)*w11;
                }
            }
        }

        *(float4*)&sm[0][ry][xq] = make_float4(rr[0], rr[1], rr[2], rr[3]);
        *(float4*)&sm[1][ry][xq] = make_float4(gg[0], gg[1], gg[2], gg[3]);
        *(float4*)&sm[2][ry][xq] = make_float4(bb[0], bb[1], bb[2], bb[3]);

        if (ry < 8) {
            float* ou = out + off_u8 + ((long long)((n * 224 + y) * 224 + xq)) * 3;
            if (group_zero) {
                float4 z = make_float4(0.f, 0.f, 0.f, 0.f);
                __stcs((float4*)(ou + 0), z);
                __stcs((float4*)(ou + 4), z);
                __stcs((float4*)(ou + 8), z);
            } else {
                float u[12];
#pragma unroll
                for (int j = 0; j < 4; j++) {
                    u[3*j+0] = (float)(unsigned char)rr[j];
                    u[3*j+1] = (float)(unsigned char)gg[j];
                    u[3*j+2] = (float)(unsigned char)bb[j];
                }
                __stcs((float4*)(ou + 0), make_float4(u[0], u[1], u[2],  u[3]));
                __stcs((float4*)(ou + 4), make_float4(u[4], u[5], u[6],  u[7]));
                __stcs((float4*)(ou + 8), make_float4(u[8], u[9], u[10], u[11]));
            }
        }
    }
    __syncthreads();

    // ---- phase 2: owned t192 rows, flat parallel loop, 4 px per item ----
    float pa = 0.57142857f, pt = 32.f;
    float pdet = pa * pa;
    float pia  = pa / pdet;      // matches reference float arithmetic
    float pitx = -(pia * pt);

    int lo = sRange[0], hi = sRange[1];
    int cnt = hi - lo + 1;
    int items2 = (cnt > 0) ? cnt * 48 : 0;
    for (int it = tid; it < items2; it += 256) {
        int dy = it / 48;
        int y  = lo + dy;
        int xq = (it - dy * 48) * 4;

        float syf = pia * (float)y + pitx;
        float y0f = floorf(syf);
        int y0 = (int)y0f;
        float fy = syf - y0f;
        int y1 = y0 + 1;
        float vy0 = (y0 >= 0 && y0 < 224) ? 1.f : 0.f;
        float vy1 = (y1 >= 0 && y1 < 224) ? 1.f : 0.f;
        int y0c = min(max(y0, 0), 223);
        int y1c = min(max(y1, 0), 223);
        int ry0 = min(max(y0c - r0, 0), 8);
        int ry1 = min(max(y1c - r0, 0), 8);
        bool rowzero = (syf <= -1.f) | (syf >= 224.f);

        float o0[4], o1[4], o2[4];
#pragma unroll
        for (int j = 0; j < 4; j++) {
            int x = xq + j;
            float sxf = pia * (float)x + pitx;
            if (rowzero | (sxf <= -1.f) | (sxf >= 224.f)) {
                o0[j] = 0.f; o1[j] = 0.f; o2[j] = 0.f;
            } else {
                float x0f = floorf(sxf);
                int x0 = (int)x0f;
                float fx = sxf - x0f;
                int x1 = x0 + 1;
                float vx0 = (x0 >= 0 && x0 < 224) ? 1.f : 0.f;
                float vx1 = (x1 >= 0 && x1 < 224) ? 1.f : 0.f;
                float w00 = (1.f - fx) * (1.f - fy) * vx0 * vy0;
                float w10 = fx         * (1.f - fy) * vx1 * vy0;
                float w01 = (1.f - fx) * fy         * vx0 * vy1;
                float w11 = fx         * fy         * vx1 * vy1;
                int x0c = min(max(x0, 0), 223);
                int x1c = min(max(x1, 0), 223);
                o0[j] = sm[0][ry0][x0c]*w00 + sm[0][ry0][x1c]*w10
                      + sm[0][ry1][x0c]*w01 + sm[0][ry1][x1c]*w11;
                o1[j] = sm[1][ry0][x0c]*w00 + sm[1][ry0][x1c]*w10
                      + sm[1][ry1][x0c]*w01 + sm[1][ry1][x1c]*w11;
                o2[j] = sm[2][ry0][x0c]*w00 + sm[2][ry0][x1c]*w10
                      + sm[2][ry1][x0c]*w01 + sm[2][ry1][x1c]*w11;
            }
        }
        long long ob = off_t192 + ((long long)(n * 3) * 192 + y) * 192 + xq;
        __stcs((float4*)(out + ob),             make_float4(o0[0], o0[1], o0[2], o0[3]));
        __stcs((float4*)(out + ob + 192*192),   make_float4(o1[0], o1[1], o1[2], o1[3]));
        __stcs((float4*)(out + ob + 2*192*192), make_float4(o2[0], o2[1], o2[2], o2[3]));
    }
}

// ---------------------------------------------------------------------------
extern "C" void kernel_launch(void* const* d_in, const int* in_sizes, int n_in,
                              void* d_out, int out_size)
{
    const float* xs  = (const float*)d_in[0];
    const float* img = (const float*)d_in[1];
    float* out = (float*)d_out;

    int N = in_sizes[0] / 10;   // (N,5,2)
    if (N > NMAX) N = NMAX;

    // output layout (float32): xs | IM_composed | imgs_u8 | t192 | M
    long long off_imc  = 10LL * N;
    long long off_u8   = off_imc + 6LL * N;
    long long off_t192 = off_u8 + 150528LL * N;   // 224*224*3
    long long off_M    = off_t192 + 110592LL * N; // 192*192*3

    prep_kernel<<<4098, 256>>>(img, xs, out, N, off_imc, off_M);
    fused_warp_kernel<<<28 * N, 256>>>(img, out, off_u8, off_t192);
}

// round 11
// speedup vs baseline: 1.5366x; 1.5366x over previous
#include <cuda_runtime.h>

#define NMAX 256

// Scratch (allocation-free rule: __device__ globals)
__device__ float4 g_img4[1024 * 1024];   // repacked source image (RGBA, pad=0)
__device__ float  g_IM[NMAX * 6];        // inverse affine per face
__device__ int2   g_rowrange[28];        // t192 rows owned by each 8-row tile

__constant__ float c_SRC[5][10] = {
    {103.284f,100.23f, 115.234f,99.98f, 71.48f,138.014f, 102.314f,178.1f,   114.05f,179.404f},
    {90.062f,100.236f, 131.136f,101.744f,79.354f,136.222f,90.354f,172.38f,  128.492f,173.516f},
    {79.46f,102.276f,  144.54f,102.276f, 112.0f,136.986f, 84.926f,174.02f,  139.074f,174.02f},
    {93.69f,101.744f,  134.764f,100.236f,145.474f,136.222f,96.334f,173.516f,134.472f,172.38f},
    {109.592f,99.98f,  121.542f,100.23f, 153.346f,138.014f,110.776f,179.404f,122.514f,178.1f}
};

// ---------------------------------------------------------------------------
// est: Umeyama over 5 templates, argmin, invert, compose. One thread/face.
// ---------------------------------------------------------------------------
__device__ void est_face(const float* __restrict__ xs, float* __restrict__ out,
                         int n, long long off_imc, long long off_M)
{
    float px[5], py[5];
#pragma unroll
    for (int i = 0; i < 5; i++) { px[i] = xs[n*10 + 2*i]; py[i] = xs[n*10 + 2*i + 1]; }

    float smx = 0.f, smy = 0.f;
#pragma unroll
    for (int i = 0; i < 5; i++) { smx += px[i]; smy += py[i]; }
    smx *= 0.2f; smy *= 0.2f;

    float sdx[5], sdy[5], var_sum = 0.f;
#pragma unroll
    for (int i = 0; i < 5; i++) {
        sdx[i] = px[i] - smx; sdy[i] = py[i] - smy;
        var_sum += sdx[i]*sdx[i] + sdy[i]*sdy[i];
    }
    var_sum *= 0.2f;

    float bestE = 3.4e38f;
    float bM[6] = {0,0,0,0,0,0};

#pragma unroll
    for (int k = 0; k < 5; k++) {
        const float* D = c_SRC[k];
        float dmx = 0.f, dmy = 0.f;
#pragma unroll
        for (int i = 0; i < 5; i++) { dmx += D[2*i]; dmy += D[2*i+1]; }
        dmx *= 0.2f; dmy *= 0.2f;

        float A00 = 0.f, A01 = 0.f, A10 = 0.f, A11 = 0.f;
#pragma unroll
        for (int i = 0; i < 5; i++) {
            float ddx = D[2*i]   - dmx;
            float ddy = D[2*i+1] - dmy;
            A00 += ddx * sdx[i]; A01 += ddx * sdy[i];
            A10 += ddy * sdx[i]; A11 += ddy * sdy[i];
        }
        A00 *= 0.2f; A01 *= 0.2f; A10 *= 0.2f; A11 *= 0.2f;

        float det = A00*A11 - A01*A10;
        float s   = (det > 0.f) ? 1.f : ((det < 0.f) ? -1.f : 0.f);

        float E = (A00 + A11) * 0.5f;
        float F = (A00 - A11) * 0.5f;
        float G = (A10 + A01) * 0.5f;
        float H = (A10 - A01) * 0.5f;
        float Q  = hypotf(E, H);
        float Rr = hypotf(F, G);
        float sxv = Q + Rr;
        float syv = Q - Rr;
        float a1 = atan2f(G, F);
        float a2 = atan2f(H, E);
        float beta  = (a2 - a1) * 0.5f;
        float gamma = (a2 + a1) * 0.5f;
        float cg = cosf(gamma), sg = sinf(gamma);
        float cb = cosf(beta),  sb = sinf(beta);
        float sgn = (syv < 0.f) ? -1.f : 1.f;
        float V00 = cb,        V01 = -sb;
        float V10 = sb * sgn,  V11 = cb * sgn;
        float R00 = cg * V00 - sg * s * V10;
        float R01 = cg * V01 - sg * s * V11;
        float R10 = sg * V00 + cg * s * V10;
        float R11 = sg * V01 + cg * s * V11;

        float scale = (sxv + fabsf(syv) * s) / var_sum;
        float tx = dmx - scale * (R00 * smx + R01 * smy);
        float ty = dmy - scale * (R10 * smx + R11 * smy);
        float M00 = scale * R00, M01 = scale * R01;
        float M10 = scale * R10, M11 = scale * R11;

        float e = 0.f;
#pragma unroll
        for (int i = 0; i < 5; i++) {
            float rx = M00*px[i] + M01*py[i] + tx - D[2*i];
            float ry = M10*px[i] + M11*py[i] + ty - D[2*i+1];
            e += sqrtf(rx*rx + ry*ry);
        }
        if (e < bestE) {
            bestE = e;
            bM[0] = M00; bM[1] = M01; bM[2] = tx;
            bM[3] = M10; bM[4] = M11; bM[5] = ty;
        }
    }

    float det = bM[0]*bM[4] - bM[1]*bM[3];
    float ia  =  bM[4] / det;
    float ib  = -bM[1] / det;
    float ic  = -bM[3] / det;
    float idd =  bM[0] / det;
    float itx = -(ia * bM[2] + ib  * bM[5]);
    float ity = -(ic * bM[2] + idd * bM[5]);

    g_IM[n*6+0] = ia;  g_IM[n*6+1] = ib;  g_IM[n*6+2] = itx;
    g_IM[n*6+3] = ic;  g_IM[n*6+4] = idd; g_IM[n*6+5] = ity;

    float pa = 0.57142857f, pt = 32.f;
    float pdet = pa * pa;
    float pia  = pa / pdet;
    float pitx = -(pia * pt);
    float C00 = ia  * pia,  C01 = ib  * pia;
    float C10 = ic  * pia,  C11 = idd * pia;
    float CT0 = ia * pitx + ib  * pitx + itx;
    float CT1 = ic * pitx + idd * pitx + ity;

#pragma unroll
    for (int j = 0; j < 10; j++) out[n*10 + j] = xs[n*10 + j];
    float* oc = out + off_imc + (long long)n * 6;
    oc[0] = C00; oc[1] = C01; oc[2] = CT0; oc[3] = C10; oc[4] = C11; oc[5] = CT1;
    float* om = out + off_M + (long long)n * 6;
    om[0] = bM[0]; om[1] = bM[1]; om[2] = bM[2]; om[3] = bM[3]; om[4] = bM[4]; om[5] = bM[5];
}

// ---------------------------------------------------------------------------
// Kernel A (prep): blocks [0,1024): img repack (4px/thread, float4 IO)
//                  block 1024: est for all faces
//                  block 1025: t192 tile row-ranges
// ---------------------------------------------------------------------------
__global__ __launch_bounds__(256) void prep_kernel(const float* __restrict__ img,
                                                   const float* __restrict__ xs,
                                                   float* __restrict__ out,
                                                   int N, long long off_imc, long long off_M)
{
    int blk = blockIdx.x;
    int tid = threadIdx.x;

    if (blk < 1024) {
        int j = blk * 256 + tid;            // 4-pixel group id, j < 262144
        const float4* im4 = (const float4*)img;
        float4 a = im4[3*j+0];
        float4 b = im4[3*j+1];
        float4 c = im4[3*j+2];
        g_img4[4*j+0] = make_float4(a.x, a.y, a.z, 0.f);
        g_img4[4*j+1] = make_float4(a.w, b.x, b.y, 0.f);
        g_img4[4*j+2] = make_float4(b.z, b.w, c.x, 0.f);
        g_img4[4*j+3] = make_float4(c.y, c.z, c.w, 0.f);
    } else if (blk == 1024) {
        if (tid < N) est_face(xs, out, tid, off_imc, off_M);
    } else {
        __shared__ int s_lo[28], s_hi[28];
        if (tid < 28) { s_lo[tid] = 192; s_hi[tid] = -1; }
        __syncthreads();
        if (tid < 192) {
            float pa = 0.57142857f, pt = 32.f;
            float pdet = pa * pa;
            float pia  = pa / pdet;
            float pitx = -(pia * pt);
            float syf = pia * (float)tid + pitx;
            int y0 = (int)floorf(syf);
            int t = (y0 < 0) ? 0 : ((y0 >= 224) ? 27 : (y0 >> 3));
            atomicMin(&s_lo[t], tid);
            atomicMax(&s_hi[t], tid);
        }
        __syncthreads();
        if (tid < 28) g_rowrange[tid] = make_int2(s_lo[tid], s_hi[tid]);
    }
}

// ---------------------------------------------------------------------------
// Kernel B (fused): per (face, 8-row tile):
//   phase 1: bilinear-warp img4 -> 9-row t224 tile in smem (+u8 output, 8 rows)
//            OOB skip (zero taps -> zero loads), streaming u8 stores
//   phase 2: 1.75x-zoom bilinear tile -> owned t192 rows, streaming stores
// ---------------------------------------------------------------------------
__global__ __launch_bounds__(256, 5) void fused_warp_kernel(float* __restrict__ out,
                                                            long long off_u8,
                                                            long long off_t192)
{
    __shared__ float sm[3][9][224];   // 24192 B tile (halo row included)
    __shared__ float sIM[6];
    __shared__ int   sRange[2];

    int blk  = blockIdx.x;
    int tile = blk % 28;
    int n    = blk / 28;
    int r0   = tile * 8;
    int tid  = threadIdx.x;

    if (tid < 6) sIM[tid] = g_IM[n*6 + tid];
    if (tid == 6) { int2 rr = g_rowrange[tile]; sRange[0] = rr.x; sRange[1] = rr.y; }
    __syncthreads();
    float i0 = sIM[0], i1 = sIM[1], i2 = sIM[2];
    float i3 = sIM[3], i4 = sIM[4], i5 = sIM[5];

    // ---- phase 1: fill t224 tile, 4 px per thread-item ----
    int rows   = (r0 + 8 < 224) ? 9 : 8;
    int items4 = rows * 56;                      // 56 groups of 4 px per row
    for (int it = tid; it < items4; it += 256) {
        int ry = it / 56;
        int xq = (it - ry * 56) * 4;
        int y  = r0 + ry;
        float gy = (float)y;

        float sxv[4], syv[4];
#pragma unroll
        for (int j = 0; j < 4; j++) {
            float gx = (float)(xq + j);
            sxv[j] = i0 * gx + i1 * gy + i2;
            syv[j] = i3 * gx + i4 * gy + i5;
        }

        // Group-level OOB skip (affine monotone along segment): all 16 taps
        // have weight 0 iff the segment lies fully outside (-1,1024)^2.
        bool group_zero =
            (sxv[0] <= -1.f   && sxv[3] <= -1.f)   ||
            (sxv[0] >= 1024.f && sxv[3] >= 1024.f) ||
            (syv[0] <= -1.f   && syv[3] <= -1.f)   ||
            (syv[0] >= 1024.f && syv[3] >= 1024.f);

        float rr[4], gg[4], bb[4];
        if (group_zero) {
#pragma unroll
            for (int j = 0; j < 4; j++) { rr[j] = 0.f; gg[j] = 0.f; bb[j] = 0.f; }
        } else {
            bool interior = (sxv[0] >= 0.f) & (sxv[0] < 1023.f) &
                            (sxv[3] >= 0.f) & (sxv[3] < 1023.f) &
                            (syv[0] >= 0.f) & (syv[0] < 1023.f) &
                            (syv[3] >= 0.f) & (syv[3] < 1023.f);
            if (interior) {
#pragma unroll
                for (int j = 0; j < 4; j++) {
                    float x0f = floorf(sxv[j]), y0f = floorf(syv[j]);
                    float fx = sxv[j] - x0f,    fy = syv[j] - y0f;
                    int x0 = (int)x0f, y0 = (int)y0f;
                    float w00 = (1.f - fx) * (1.f - fy);
                    float w10 = fx         * (1.f - fy);
                    float w01 = (1.f - fx) * fy;
                    float w11 = fx         * fy;
                    int base0 = y0 * 1024 + x0;
                    float4 v00 = g_img4[base0];
                    float4 v10 = g_img4[base0 + 1];
                    float4 v01 = g_img4[base0 + 1024];
                    float4 v11 = g_img4[base0 + 1025];
                    rr[j] = v00.x*w00 + v10.x*w10 + v01.x*w01 + v11.x*w11;
                    gg[j] = v00.y*w00 + v10.y*w10 + v01.y*w01 + v11.y*w11;
                    bb[j] = v00.z*w00 + v10.z*w10 + v01.z*w01 + v11.z*w11;
                }
            } else {
#pragma unroll
                for (int j = 0; j < 4; j++) {
                    // per-pixel OOB skip
                    if (sxv[j] <= -1.f || sxv[j] >= 1024.f ||
                        syv[j] <= -1.f || syv[j] >= 1024.f) {
                        rr[j] = 0.f; gg[j] = 0.f; bb[j] = 0.f;
                        continue;
                    }
                    float x0f = floorf(sxv[j]), y0f = floorf(syv[j]);
                    float fx = sxv[j] - x0f,    fy = syv[j] - y0f;
                    int x0 = (int)x0f, y0 = (int)y0f;
                    int x1 = x0 + 1,   y1 = y0 + 1;
                    const int W = 1024, H = 1024;
                    float vx0 = (x0 >= 0 && x0 < W) ? 1.f : 0.f;
                    float vx1 = (x1 >= 0 && x1 < W) ? 1.f : 0.f;
                    float vy0 = (y0 >= 0 && y0 < H) ? 1.f : 0.f;
                    float vy1 = (y1 >= 0 && y1 < H) ? 1.f : 0.f;
                    float w00 = (1.f - fx) * (1.f - fy) * vx0 * vy0;
                    float w10 = fx         * (1.f - fy) * vx1 * vy0;
                    float w01 = (1.f - fx) * fy         * vx0 * vy1;
                    float w11 = fx         * fy         * vx1 * vy1;
                    int x0c = min(max(x0, 0), W-1), x1c = min(max(x1, 0), W-1);
                    int y0c = min(max(y0, 0), H-1), y1c = min(max(y1, 0), H-1);
                    float4 v00 = g_img4[y0c * W + x0c];
                    float4 v10 = g_img4[y0c * W + x1c];
                    float4 v01 = g_img4[y1c * W + x0c];
                    float4 v11 = g_img4[y1c * W + x1c];
                    rr[j] = v00.x*w00 + v10.x*w10 + v01.x*w01 + v11.x*w11;
                    gg[j] = v00.y*w00 + v10.y*w10 + v01.y*w01 + v11.y*w11;
                    bb[j] = v00.z*w00 + v10.z*w10 + v01.z*w01 + v11.z*w11;
                }
            }
        }

        *(float4*)&sm[0][ry][xq] = make_float4(rr[0], rr[1], rr[2], rr[3]);
        *(float4*)&sm[1][ry][xq] = make_float4(gg[0], gg[1], gg[2], gg[3]);
        *(float4*)&sm[2][ry][xq] = make_float4(bb[0], bb[1], bb[2], bb[3]);

        if (ry < 8) {
            float* ou = out + off_u8 + ((long long)((n * 224 + y) * 224 + xq)) * 3;
            if (group_zero) {
                float4 z = make_float4(0.f, 0.f, 0.f, 0.f);
                __stcs((float4*)(ou + 0), z);
                __stcs((float4*)(ou + 4), z);
                __stcs((float4*)(ou + 8), z);
            } else {
                float u[12];
#pragma unroll
                for (int j = 0; j < 4; j++) {
                    u[3*j+0] = (float)(unsigned char)rr[j];
                    u[3*j+1] = (float)(unsigned char)gg[j];
                    u[3*j+2] = (float)(unsigned char)bb[j];
                }
                __stcs((float4*)(ou + 0), make_float4(u[0], u[1], u[2],  u[3]));
                __stcs((float4*)(ou + 4), make_float4(u[4], u[5], u[6],  u[7]));
                __stcs((float4*)(ou + 8), make_float4(u[8], u[9], u[10], u[11]));
            }
        }
    }
    __syncthreads();

    // ---- phase 2: owned t192 rows, flat parallel loop, 4 px per item ----
    float pa = 0.57142857f, pt = 32.f;
    float pdet = pa * pa;
    float pia  = pa / pdet;      // matches reference float arithmetic
    float pitx = -(pia * pt);

    int lo = sRange[0], hi = sRange[1];
    int cnt = hi - lo + 1;
    int items2 = (cnt > 0) ? cnt * 48 : 0;
    for (int it = tid; it < items2; it += 256) {
        int dy = it / 48;
        int y  = lo + dy;
        int xq = (it - dy * 48) * 4;

        float syf = pia * (float)y + pitx;
        float y0f = floorf(syf);
        int y0 = (int)y0f;
        float fy = syf - y0f;
        int y1 = y0 + 1;
        float vy0 = (y0 >= 0 && y0 < 224) ? 1.f : 0.f;
        float vy1 = (y1 >= 0 && y1 < 224) ? 1.f : 0.f;
        int y0c = min(max(y0, 0), 223);
        int y1c = min(max(y1, 0), 223);
        int ry0 = min(max(y0c - r0, 0), 8);
        int ry1 = min(max(y1c - r0, 0), 8);
        bool rowzero = (syf <= -1.f) | (syf >= 224.f);

        float o0[4], o1[4], o2[4];
#pragma unroll
        for (int j = 0; j < 4; j++) {
            int x = xq + j;
            float sxf = pia * (float)x + pitx;
            if (rowzero | (sxf <= -1.f) | (sxf >= 224.f)) {
                o0[j] = 0.f; o1[j] = 0.f; o2[j] = 0.f;
            } else {
                float x0f = floorf(sxf);
                int x0 = (int)x0f;
                float fx = sxf - x0f;
                int x1 = x0 + 1;
                float vx0 = (x0 >= 0 && x0 < 224) ? 1.f : 0.f;
                float vx1 = (x1 >= 0 && x1 < 224) ? 1.f : 0.f;
                float w00 = (1.f - fx) * (1.f - fy) * vx0 * vy0;
                float w10 = fx         * (1.f - fy) * vx1 * vy0;
                float w01 = (1.f - fx) * fy         * vx0 * vy1;
                float w11 = fx         * fy         * vx1 * vy1;
                int x0c = min(max(x0, 0), 223);
                int x1c = min(max(x1, 0), 223);
                o0[j] = sm[0][ry0][x0c]*w00 + sm[0][ry0][x1c]*w10
                      + sm[0][ry1][x0c]*w01 + sm[0][ry1][x1c]*w11;
                o1[j] = sm[1][ry0][x0c]*w00 + sm[1][ry0][x1c]*w10
                      + sm[1][ry1][x0c]*w01 + sm[1][ry1][x1c]*w11;
                o2[j] = sm[2][ry0][x0c]*w00 + sm[2][ry0][x1c]*w10
                      + sm[2][ry1][x0c]*w01 + sm[2][ry1][x1c]*w11;
            }
        }
        long long ob = off_t192 + ((long long)(n * 3) * 192 + y) * 192 + xq;
        __stcs((float4*)(out + ob),             make_float4(o0[0], o0[1], o0[2], o0[3]));
        __stcs((float4*)(out + ob + 192*192),   make_float4(o1[0], o1[1], o1[2], o1[3]));
        __stcs((float4*)(out + ob + 2*192*192), make_float4(o2[0], o2[1], o2[2], o2[3]));
    }
}

// ---------------------------------------------------------------------------
extern "C" void kernel_launch(void* const* d_in, const int* in_sizes, int n_in,
                              void* d_out, int out_size)
{
    const float* xs  = (const float*)d_in[0];
    const float* img = (const float*)d_in[1];
    float* out = (float*)d_out;

    int N = in_sizes[0] / 10;   // (N,5,2)
    if (N > NMAX) N = NMAX;

    // output layout (float32): xs | IM_composed | imgs_u8 | t192 | M
    long long off_imc  = 10LL * N;
    long long off_u8   = off_imc + 6LL * N;
    long long off_t192 = off_u8 + 150528LL * N;   // 224*224*3
    long long off_M    = off_t192 + 110592LL * N; // 192*192*3

    prep_kernel<<<1026, 256>>>(img, xs, out, N, off_imc, off_M);
    fused_warp_kernel<<<28 * N, 256>>>(out, off_u8, off_t192);
}

// round 14
// speedup vs baseline: 1.6597x; 1.0801x over previous
#include <cuda_runtime.h>

#define NMAX 256

// Scratch (allocation-free rule: __device__ globals)
__device__ float4 g_img4[1024 * 1024];   // repacked source image (RGBA, pad=0)
__device__ float  g_IM[NMAX * 6];        // inverse affine per face
__device__ int2   g_rowrange[28];        // t192 rows owned by each 8-row tile

__constant__ float c_SRC[5][10] = {
    {103.284f,100.23f, 115.234f,99.98f, 71.48f,138.014f, 102.314f,178.1f,   114.05f,179.404f},
    {90.062f,100.236f, 131.136f,101.744f,79.354f,136.222f,90.354f,172.38f,  128.492f,173.516f},
    {79.46f,102.276f,  144.54f,102.276f, 112.0f,136.986f, 84.926f,174.02f,  139.074f,174.02f},
    {93.69f,101.744f,  134.764f,100.236f,145.474f,136.222f,96.334f,173.516f,134.472f,172.38f},
    {109.592f,99.98f,  121.542f,100.23f, 153.346f,138.014f,110.776f,179.404f,122.514f,178.1f}
};

// ---------------------------------------------------------------------------
// est: Umeyama over 5 templates, argmin, invert, compose. One thread/face.
// ---------------------------------------------------------------------------
__device__ void est_face(const float* __restrict__ xs, float* __restrict__ out,
                         int n, long long off_imc, long long off_M)
{
    float px[5], py[5];
#pragma unroll
    for (int i = 0; i < 5; i++) { px[i] = xs[n*10 + 2*i]; py[i] = xs[n*10 + 2*i + 1]; }

    float smx = 0.f, smy = 0.f;
#pragma unroll
    for (int i = 0; i < 5; i++) { smx += px[i]; smy += py[i]; }
    smx *= 0.2f; smy *= 0.2f;

    float sdx[5], sdy[5], var_sum = 0.f;
#pragma unroll
    for (int i = 0; i < 5; i++) {
        sdx[i] = px[i] - smx; sdy[i] = py[i] - smy;
        var_sum += sdx[i]*sdx[i] + sdy[i]*sdy[i];
    }
    var_sum *= 0.2f;

    float bestE = 3.4e38f;
    float bM[6] = {0,0,0,0,0,0};

#pragma unroll
    for (int k = 0; k < 5; k++) {
        const float* D = c_SRC[k];
        float dmx = 0.f, dmy = 0.f;
#pragma unroll
        for (int i = 0; i < 5; i++) { dmx += D[2*i]; dmy += D[2*i+1]; }
        dmx *= 0.2f; dmy *= 0.2f;

        float A00 = 0.f, A01 = 0.f, A10 = 0.f, A11 = 0.f;
#pragma unroll
        for (int i = 0; i < 5; i++) {
            float ddx = D[2*i]   - dmx;
            float ddy = D[2*i+1] - dmy;
            A00 += ddx * sdx[i]; A01 += ddx * sdy[i];
            A10 += ddy * sdx[i]; A11 += ddy * sdy[i];
        }
        A00 *= 0.2f; A01 *= 0.2f; A10 *= 0.2f; A11 *= 0.2f;

        float det = A00*A11 - A01*A10;
        float s   = (det > 0.f) ? 1.f : ((det < 0.f) ? -1.f : 0.f);

        float E = (A00 + A11) * 0.5f;
        float F = (A00 - A11) * 0.5f;
        float G = (A10 + A01) * 0.5f;
        float H = (A10 - A01) * 0.5f;
        float Q  = hypotf(E, H);
        float Rr = hypotf(F, G);
        float sxv = Q + Rr;
        float syv = Q - Rr;
        float a1 = atan2f(G, F);
        float a2 = atan2f(H, E);
        float beta  = (a2 - a1) * 0.5f;
        float gamma = (a2 + a1) * 0.5f;
        float cg = cosf(gamma), sg = sinf(gamma);
        float cb = cosf(beta),  sb = sinf(beta);
        float sgn = (syv < 0.f) ? -1.f : 1.f;
        float V00 = cb,        V01 = -sb;
        float V10 = sb * sgn,  V11 = cb * sgn;
        float R00 = cg * V00 - sg * s * V10;
        float R01 = cg * V01 - sg * s * V11;
        float R10 = sg * V00 + cg * s * V10;
        float R11 = sg * V01 + cg * s * V11;

        float scale = (sxv + fabsf(syv) * s) / var_sum;
        float tx = dmx - scale * (R00 * smx + R01 * smy);
        float ty = dmy - scale * (R10 * smx + R11 * smy);
        float M00 = scale * R00, M01 = scale * R01;
        float M10 = scale * R10, M11 = scale * R11;

        float e = 0.f;
#pragma unroll
        for (int i = 0; i < 5; i++) {
            float rx = M00*px[i] + M01*py[i] + tx - D[2*i];
            float ry = M10*px[i] + M11*py[i] + ty - D[2*i+1];
            e += sqrtf(rx*rx + ry*ry);
        }
        if (e < bestE) {
            bestE = e;
            bM[0] = M00; bM[1] = M01; bM[2] = tx;
            bM[3] = M10; bM[4] = M11; bM[5] = ty;
        }
    }

    float det = bM[0]*bM[4] - bM[1]*bM[3];
    float ia  =  bM[4] / det;
    float ib  = -bM[1] / det;
    float ic  = -bM[3] / det;
    float idd =  bM[0] / det;
    float itx = -(ia * bM[2] + ib  * bM[5]);
    float ity = -(ic * bM[2] + idd * bM[5]);

    g_IM[n*6+0] = ia;  g_IM[n*6+1] = ib;  g_IM[n*6+2] = itx;
    g_IM[n*6+3] = ic;  g_IM[n*6+4] = idd; g_IM[n*6+5] = ity;

    float pa = 0.57142857f, pt = 32.f;
    float pdet = pa * pa;
    float pia  = pa / pdet;
    float pitx = -(pia * pt);
    float C00 = ia  * pia,  C01 = ib  * pia;
    float C10 = ic  * pia,  C11 = idd * pia;
    float CT0 = ia * pitx + ib  * pitx + itx;
    float CT1 = ic * pitx + idd * pitx + ity;

#pragma unroll
    for (int j = 0; j < 10; j++) out[n*10 + j] = xs[n*10 + j];
    float* oc = out + off_imc + (long long)n * 6;
    oc[0] = C00; oc[1] = C01; oc[2] = CT0; oc[3] = C10; oc[4] = C11; oc[5] = CT1;
    float* om = out + off_M + (long long)n * 6;
    om[0] = bM[0]; om[1] = bM[1]; om[2] = bM[2]; om[3] = bM[3]; om[4] = bM[4]; om[5] = bM[5];
}

// ---------------------------------------------------------------------------
// Kernel A (prep): blocks [0,1024): img repack (4px/thread, float4 IO)
//                  block 1024: est for all faces
//                  block 1025: t192 tile row-ranges
// ---------------------------------------------------------------------------
__global__ __launch_bounds__(256) void prep_kernel(const float* __restrict__ img,
                                                   const float* __restrict__ xs,
                                                   float* __restrict__ out,
                                                   int N, long long off_imc, long long off_M)
{
    int blk = blockIdx.x;
    int tid = threadIdx.x;

    if (blk < 1024) {
        int j = blk * 256 + tid;            // 4-pixel group id, j < 262144
        const float4* im4 = (const float4*)img;
        float4 a = im4[3*j+0];
        float4 b = im4[3*j+1];
        float4 c = im4[3*j+2];
        g_img4[4*j+0] = make_float4(a.x, a.y, a.z, 0.f);
        g_img4[4*j+1] = make_float4(a.w, b.x, b.y, 0.f);
        g_img4[4*j+2] = make_float4(b.z, b.w, c.x, 0.f);
        g_img4[4*j+3] = make_float4(c.y, c.z, c.w, 0.f);
    } else if (blk == 1024) {
        if (tid < N) est_face(xs, out, tid, off_imc, off_M);
    } else {
        __shared__ int s_lo[28], s_hi[28];
        if (tid < 28) { s_lo[tid] = 192; s_hi[tid] = -1; }
        __syncthreads();
        if (tid < 192) {
            float pa = 0.57142857f, pt = 32.f;
            float pdet = pa * pa;
            float pia  = pa / pdet;
            float pitx = -(pia * pt);
            float syf = pia * (float)tid + pitx;
            int y0 = (int)floorf(syf);
            int t = (y0 < 0) ? 0 : ((y0 >= 224) ? 27 : (y0 >> 3));
            atomicMin(&s_lo[t], tid);
            atomicMax(&s_hi[t], tid);
        }
        __syncthreads();
        if (tid < 28) g_rowrange[tid] = make_int2(s_lo[tid], s_hi[tid]);
    }
}

// ---------------------------------------------------------------------------
// Kernel B (fused): per (face, 8-row tile):
//   phase 1a: bilinear-warp img4 -> 9-row t224 tile in smem, ONE px/thread so
//             warp lanes are adjacent in source space (line sharing in L1tex)
//   phase 1b: u8 output from smem tile, vectorized float4 streaming stores
//   phase 2:  1.75x-zoom bilinear tile -> owned t192 rows, streaming stores
// ---------------------------------------------------------------------------
__global__ __launch_bounds__(256, 5) void fused_warp_kernel(float* __restrict__ out,
                                                            long long off_u8,
                                                            long long off_t192)
{
    __shared__ float sm[3][9][224];   // 24192 B tile (halo row included)
    __shared__ float sIM[6];
    __shared__ int   sRange[2];

    int blk  = blockIdx.x;
    int tile = blk % 28;
    int n    = blk / 28;
    int r0   = tile * 8;
    int tid  = threadIdx.x;

    if (tid < 6) sIM[tid] = g_IM[n*6 + tid];
    if (tid == 6) { int2 rr = g_rowrange[tile]; sRange[0] = rr.x; sRange[1] = rr.y; }
    __syncthreads();
    float i0 = sIM[0], i1 = sIM[1], i2 = sIM[2];
    float i3 = sIM[3], i4 = sIM[4], i5 = sIM[5];

    // ---- phase 1a: fill t224 tile, 1 px per thread (lanes adjacent in src) ----
    int rows  = (r0 + 8 < 224) ? 9 : 8;
    int items = rows * 224;
    for (int p = tid; p < items; p += 256) {
        int ry = p / 224;
        int x  = p - ry * 224;
        int y  = r0 + ry;

        float gx = (float)x, gy = (float)y;
        float sx = i0 * gx + i1 * gy + i2;
        float sy = i3 * gx + i4 * gy + i5;

        float r, g, b;
        if (sx <= -1.f || sx >= 1024.f || sy <= -1.f || sy >= 1024.f) {
            // all 4 taps have zero weight: no loads
            r = 0.f; g = 0.f; b = 0.f;
        } else if (sx >= 0.f && sx < 1023.f && sy >= 0.f && sy < 1023.f) {
            // interior fast path: no masks, no clamps
            float x0f = floorf(sx), y0f = floorf(sy);
            float fx = sx - x0f,    fy = sy - y0f;
            int x0 = (int)x0f, y0 = (int)y0f;
            float w00 = (1.f - fx) * (1.f - fy);
            float w10 = fx         * (1.f - fy);
            float w01 = (1.f - fx) * fy;
            float w11 = fx         * fy;
            int base0 = y0 * 1024 + x0;
            float4 v00 = g_img4[base0];
            float4 v10 = g_img4[base0 + 1];
            float4 v01 = g_img4[base0 + 1024];
            float4 v11 = g_img4[base0 + 1025];
            r = v00.x*w00 + v10.x*w10 + v01.x*w01 + v11.x*w11;
            g = v00.y*w00 + v10.y*w10 + v01.y*w01 + v11.y*w11;
            b = v00.z*w00 + v10.z*w10 + v01.z*w01 + v11.z*w11;
        } else {
            // border: masked + clamped (exact reference semantics)
            float x0f = floorf(sx), y0f = floorf(sy);
            float fx = sx - x0f,    fy = sy - y0f;
            int x0 = (int)x0f, y0 = (int)y0f;
            int x1 = x0 + 1,   y1 = y0 + 1;
            const int W = 1024, H = 1024;
            float vx0 = (x0 >= 0 && x0 < W) ? 1.f : 0.f;
            float vx1 = (x1 >= 0 && x1 < W) ? 1.f : 0.f;
            float vy0 = (y0 >= 0 && y0 < H) ? 1.f : 0.f;
            float vy1 = (y1 >= 0 && y1 < H) ? 1.f : 0.f;
            float w00 = (1.f - fx) * (1.f - fy) * vx0 * vy0;
            float w10 = fx         * (1.f - fy) * vx1 * vy0;
            float w01 = (1.f - fx) * fy         * vx0 * vy1;
            float w11 = fx         * fy         * vx1 * vy1;
            int x0c = min(max(x0, 0), W-1), x1c = min(max(x1, 0), W-1);
            int y0c = min(max(y0, 0), H-1), y1c = min(max(y1, 0), H-1);
            float4 v00 = g_img4[y0c * W + x0c];
            float4 v10 = g_img4[y0c * W + x1c];
            float4 v01 = g_img4[y1c * W + x0c];
            float4 v11 = g_img4[y1c * W + x1c];
            r = v00.x*w00 + v10.x*w10 + v01.x*w01 + v11.x*w11;
            g = v00.y*w00 + v10.y*w10 + v01.y*w01 + v11.y*w11;
            b = v00.z*w00 + v10.z*w10 + v01.z*w01 + v11.z*w11;
        }

        sm[0][ry][x] = r;
        sm[1][ry][x] = g;
        sm[2][ry][x] = b;
    }
    __syncthreads();

    // ---- phase 1b: u8 output from smem, 4 px per item, float4 stores ----
    for (int it = tid; it < 8 * 56; it += 256) {
        int ry = it / 56;
        int xq = (it - ry * 56) * 4;
        int y  = r0 + ry;
        float4 R = *(float4*)&sm[0][ry][xq];
        float4 G = *(float4*)&sm[1][ry][xq];
        float4 B = *(float4*)&sm[2][ry][xq];
        float u0  = (float)(unsigned char)R.x;
        float u1  = (float)(unsigned char)G.x;
        float u2  = (float)(unsigned char)B.x;
        float u3  = (float)(unsigned char)R.y;
        float u4  = (float)(unsigned char)G.y;
        float u5  = (float)(unsigned char)B.y;
        float u6  = (float)(unsigned char)R.z;
        float u7  = (float)(unsigned char)G.z;
        float u8v = (float)(unsigned char)B.z;
        float u9  = (float)(unsigned char)R.w;
        float u10 = (float)(unsigned char)G.w;
        float u11 = (float)(unsigned char)B.w;
        float* ou = out + off_u8 + ((long long)((n * 224 + y) * 224 + xq)) * 3;
        __stcs((float4*)(ou + 0), make_float4(u0, u1, u2,  u3));
        __stcs((float4*)(ou + 4), make_float4(u4, u5, u6,  u7));
        __stcs((float4*)(ou + 8), make_float4(u8v, u9, u10, u11));
    }

    // ---- phase 2: owned t192 rows, flat parallel loop, 4 px per item ----
    float pa = 0.57142857f, pt = 32.f;
    float pdet = pa * pa;
    float pia  = pa / pdet;      // matches reference float arithmetic
    float pitx = -(pia * pt);

    int lo = sRange[0], hi = sRange[1];
    int cnt = hi - lo + 1;
    int items2 = (cnt > 0) ? cnt * 48 : 0;
    for (int it = tid; it < items2; it += 256) {
        int dy = it / 48;
        int y  = lo + dy;
        int xq = (it - dy * 48) * 4;

        float syf = pia * (float)y + pitx;
        float y0f = floorf(syf);
        int y0 = (int)y0f;
        float fy = syf - y0f;
        int y1 = y0 + 1;
        float vy0 = (y0 >= 0 && y0 < 224) ? 1.f : 0.f;
        float vy1 = (y1 >= 0 && y1 < 224) ? 1.f : 0.f;
        int y0c = min(max(y0, 0), 223);
        int y1c = min(max(y1, 0), 223);
        int ry0 = min(max(y0c - r0, 0), 8);
        int ry1 = min(max(y1c - r0, 0), 8);
        bool rowzero = (syf <= -1.f) | (syf >= 224.f);

        float o0[4], o1[4], o2[4];
#pragma unroll
        for (int j = 0; j < 4; j++) {
            int x = xq + j;
            float sxf = pia * (float)x + pitx;
            if (rowzero | (sxf <= -1.f) | (sxf >= 224.f)) {
                o0[j] = 0.f; o1[j] = 0.f; o2[j] = 0.f;
            } else {
                float x0f = floorf(sxf);
                int x0 = (int)x0f;
                float fx = sxf - x0f;
                int x1 = x0 + 1;
                float vx0 = (x0 >= 0 && x0 < 224) ? 1.f : 0.f;
                float vx1 = (x1 >= 0 && x1 < 224) ? 1.f : 0.f;
                float w00 = (1.f - fx) * (1.f - fy) * vx0 * vy0;
                float w10 = fx         * (1.f - fy) * vx1 * vy0;
                float w01 = (1.f - fx) * fy         * vx0 * vy1;
                float w11 = fx         * fy         * vx1 * vy1;
                int x0c = min(max(x0, 0), 223);
                int x1c = min(max(x1, 0), 223);
                o0[j] = sm[0][ry0][x0c]*w00 + sm[0][ry0][x1c]*w10
                      + sm[0][ry1][x0c]*w01 + sm[0][ry1][x1c]*w11;
                o1[j] = sm[1][ry0][x0c]*w00 + sm[1][ry0][x1c]*w10
                      + sm[1][ry1][x0c]*w01 + sm[1][ry1][x1c]*w11;
                o2[j] = sm[2][ry0][x0c]*w00 + sm[2][ry0][x1c]*w10
                      + sm[2][ry1][x0c]*w01 + sm[2][ry1][x1c]*w11;
            }
        }
        long long ob = off_t192 + ((long long)(n * 3) * 192 + y) * 192 + xq;
        __stcs((float4*)(out + ob),             make_float4(o0[0], o0[1], o0[2], o0[3]));
        __stcs((float4*)(out + ob + 192*192),   make_float4(o1[0], o1[1], o1[2], o1[3]));
        __stcs((float4*)(out + ob + 2*192*192), make_float4(o2[0], o2[1], o2[2], o2[3]));
    }
}

// ---------------------------------------------------------------------------
extern "C" void kernel_launch(void* const* d_in, const int* in_sizes, int n_in,
                              void* d_out, int out_size)
{
    const float* xs  = (const float*)d_in[0];
    const float* img = (const float*)d_in[1];
    float* out = (float*)d_out;

    int N = in_sizes[0] / 10;   // (N,5,2)
    if (N > NMAX) N = NMAX;

    // output layout (float32): xs | IM_composed | imgs_u8 | t192 | M
    long long off_imc  = 10LL * N;
    long long off_u8   = off_imc + 6LL * N;
    long long off_t192 = off_u8 + 150528LL * N;   // 224*224*3
    long long off_M    = off_t192 + 110592LL * N; // 192*192*3

    prep_kernel<<<1026, 256>>>(img, xs, out, N, off_imc, off_M);
    fused_warp_kernel<<<28 * N, 256>>>(out, off_u8, off_t192);
}